// round 4
// baseline (speedup 1.0000x reference)
#include <cuda_runtime.h>
#include <cuda_bf16.h>

// Problem constants (fixed shapes)
#define BB 8
#define LL 512
#define DD 1024
#define NN 8192
#define GD 64
#define KK 256          // kept tokens per batch (= L - r_step, r_step = 256)
#define TL 8            // top-K candidate list length per row
#define TLP 9           // padded smem stride (bank-conflict break)

// ---------------- scratch (device globals; no allocation allowed) ----------------
__device__ float               g_gu[BB * LL * GD];     // normalized group embeddings
__device__ float               g_gn[BB * LL];          // raw norms (merge weights)
__device__ float               g_sim[BB * LL * LL];    // full sim matrix per batch
__device__ unsigned long long  g_lists[BB * LL * TL];  // per-row top-8 keys
__device__ int4                g_pairs[BB * KK];       // {i, j, bits(wi), bits(wj)} per kept slot

// float -> totally-ordered ascending unsigned
__device__ __forceinline__ unsigned ordf(float f) {
    unsigned u = __float_as_uint(f);
    return (u & 0x80000000u) ? ~u : (u | 0x80000000u);
}

// build key: ascending key == descending sim, tie-break (i,j) lexicographic
__device__ __forceinline__ unsigned long long mkkey(float s, int r, int cc) {
    int a = min(r, cc), d = max(r, cc);
    return ((unsigned long long)(~ordf(s)) << 18) | (unsigned)((a << 9) | d);
}

// =====================================================================
// K1: g = x @ W^T, then gn, gu. 128 blocks x 128 thr.
// Thread tile 4 rows x 4 cols; rg = tid&7 (rows), cg = tid>>3 (cols).
// Loads are 4/8-way broadcasts -> conflict-free; FFMA-balanced.
// Accumulation order over k is sequential 0..1023 (matches prior rounds).
// =====================================================================
__global__ void __launch_bounds__(128) k_proj(const float* __restrict__ x,
                                              const float* __restrict__ W) {
    __shared__ float xs[32][65];
    __shared__ float ws[64][65];
    __shared__ float rowsq[32][17];
    __shared__ float gn_s[32], inv_s[32];

    const int tid = threadIdx.x;
    const int rowBase = blockIdx.x * 32;
    const int rg = tid & 7, cg = tid >> 3;          // 8 x 16
    const int r0 = rg * 4, c0 = cg * 4;

    float acc[4][4];
#pragma unroll
    for (int u = 0; u < 4; u++)
#pragma unroll
        for (int v = 0; v < 4; v++) acc[u][v] = 0.f;

    for (int kc = 0; kc < DD; kc += 64) {
#pragma unroll
        for (int it = 0; it < 4; it++) {            // xs: 512 float4
            int idx = tid + it * 128;
            int rr = idx >> 4, kk = (idx & 15) << 2;
            float4 v = *reinterpret_cast<const float4*>(
                &x[(size_t)(rowBase + rr) * DD + kc + kk]);
            xs[rr][kk] = v.x; xs[rr][kk + 1] = v.y; xs[rr][kk + 2] = v.z; xs[rr][kk + 3] = v.w;
        }
#pragma unroll
        for (int it = 0; it < 8; it++) {            // ws: 1024 float4
            int idx = tid + it * 128;
            int rr = idx >> 4, kk = (idx & 15) << 2;
            float4 v = *reinterpret_cast<const float4*>(
                &W[(size_t)rr * DD + kc + kk]);
            ws[rr][kk] = v.x; ws[rr][kk + 1] = v.y; ws[rr][kk + 2] = v.z; ws[rr][kk + 3] = v.w;
        }
        __syncthreads();
#pragma unroll 4
        for (int k = 0; k < 64; k++) {
            float a[4], bv[4];
#pragma unroll
            for (int u = 0; u < 4; u++) a[u] = xs[r0 + u][k];
#pragma unroll
            for (int v = 0; v < 4; v++) bv[v] = ws[c0 + v][k];
#pragma unroll
            for (int u = 0; u < 4; u++)
#pragma unroll
                for (int v = 0; v < 4; v++)
                    acc[u][v] = fmaf(a[u], bv[v], acc[u][v]);
        }
        __syncthreads();
    }
    // row norms: partial sum of squares per thread -> smem -> 32 reducers
#pragma unroll
    for (int u = 0; u < 4; u++) {
        float s = 0.f;
#pragma unroll
        for (int v = 0; v < 4; v++) s = fmaf(acc[u][v], acc[u][v], s);
        rowsq[r0 + u][cg] = s;
    }
    __syncthreads();
    if (tid < 32) {
        float s = 0.f;
#pragma unroll
        for (int c = 0; c < 16; c++) s += rowsq[tid][c];
        float m = sqrtf(s);
        g_gn[rowBase + tid] = m;
        gn_s[tid] = m;
        inv_s[tid] = 1.f / fmaxf(m, 1e-12f);
    }
    __syncthreads();
#pragma unroll
    for (int u = 0; u < 4; u++) {
        float iv = inv_s[r0 + u];
        float4 o;
        o.x = acc[u][0] * iv; o.y = acc[u][1] * iv;
        o.z = acc[u][2] * iv; o.w = acc[u][3] * iv;
        *reinterpret_cast<float4*>(&g_gu[(size_t)(rowBase + r0 + u) * GD + c0]) = o;
    }
    (void)gn_s;
}

// =====================================================================
// K2: sim = gu @ gu^T; 32x32 tiles, 64 threads, thread = 4x4.
// sim bitwise symmetric (same k-order both sides) — required.
// =====================================================================
__global__ void __launch_bounds__(64) k_sim() {
    __shared__ float A[32][65], Bm[32][65];
    const int b = blockIdx.z, i0 = blockIdx.y * 32, j0 = blockIdx.x * 32;
    const int tid = threadIdx.x;
#pragma unroll
    for (int it = 0; it < 8; it++) {                // each tile 512 float4
        int idx = tid + it * 64;
        int rr = idx >> 4, kk = (idx & 15) << 2;
        float4 v = *reinterpret_cast<const float4*>(
            &g_gu[((size_t)b * LL + i0 + rr) * GD + kk]);
        A[rr][kk] = v.x; A[rr][kk + 1] = v.y; A[rr][kk + 2] = v.z; A[rr][kk + 3] = v.w;
        float4 w = *reinterpret_cast<const float4*>(
            &g_gu[((size_t)b * LL + j0 + rr) * GD + kk]);
        Bm[rr][kk] = w.x; Bm[rr][kk + 1] = w.y; Bm[rr][kk + 2] = w.z; Bm[rr][kk + 3] = w.w;
    }
    __syncthreads();
    const int rg = tid & 7, cg = tid >> 3;          // 8 x 8
    const int r0 = rg * 4, c0 = cg * 4;
    float acc[4][4];
#pragma unroll
    for (int u = 0; u < 4; u++)
#pragma unroll
        for (int v = 0; v < 4; v++) acc[u][v] = 0.f;
#pragma unroll 8
    for (int k = 0; k < GD; k++) {
        float a[4], bv[4];
#pragma unroll
        for (int u = 0; u < 4; u++) a[u] = A[r0 + u][k];
#pragma unroll
        for (int v = 0; v < 4; v++) bv[v] = Bm[c0 + v][k];
#pragma unroll
        for (int u = 0; u < 4; u++)
#pragma unroll
            for (int v = 0; v < 4; v++)
                acc[u][v] = fmaf(a[u], bv[v], acc[u][v]);
    }
#pragma unroll
    for (int u = 0; u < 4; u++) {
        float4 o;
        o.x = acc[u][0]; o.y = acc[u][1]; o.z = acc[u][2]; o.w = acc[u][3];
        *reinterpret_cast<float4*>(
            &g_sim[((size_t)b * LL + i0 + r0 + u) * LL + j0 + c0]) = o;
    }
}

// =====================================================================
// K3: per-row top-8 candidate keys (ascending). Warp per row.
// =====================================================================
__global__ void __launch_bounds__(256) k_lists() {
    const int warp = threadIdx.x >> 5, lane = threadIdx.x & 31;
    const int rr = blockIdx.x * 8 + warp;      // 0..4095 flattened
    const int r = rr & (LL - 1);
    const float4* row4 = reinterpret_cast<const float4*>(&g_sim[(size_t)rr * LL]);
    unsigned long long keys[16];
#pragma unroll
    for (int q = 0; q < 4; q++) {
        float4 v = row4[lane + q * 32];
        float f[4] = {v.x, v.y, v.z, v.w};
        int cbase = (lane + q * 32) * 4;
#pragma unroll
        for (int e = 0; e < 4; e++) {
            int cc = cbase + e;
            keys[q * 4 + e] = (cc == r) ? ~0ULL : mkkey(f[e], r, cc);
        }
    }
    unsigned long long* out = &g_lists[(size_t)rr * TL];
    for (int t = 0; t < TL; t++) {
        unsigned long long m = ~0ULL;
#pragma unroll
        for (int q = 0; q < 16; q++) m = keys[q] < m ? keys[q] : m;
#pragma unroll
        for (int o = 16; o; o >>= 1) {
            unsigned long long o2 = __shfl_xor_sync(0xffffffffu, m, o);
            m = o2 < m ? o2 : m;
        }
        if (lane == 0) out[t] = m;
#pragma unroll
        for (int q = 0; q < 16; q++) if (keys[q] == m) keys[q] = ~0ULL;
    }
}

// =====================================================================
// K4: greedy matching via iterated mutual-best rounds, smem top-8 lists,
// and LIST REFILL on rescan (full rescan rebuilds a fresh top-8 list, so
// endgame rows survive ~8 deaths per L2 row read instead of 1).
// Selected set identical to sequential greedy.
// =====================================================================
__global__ void __launch_bounds__(512) k_greedy() {
    extern __shared__ unsigned long long sl[];   // LL*TLP keys (36.9 KB)
    __shared__ unsigned long long best[LL];
    __shared__ unsigned char hd[LL];
    __shared__ unsigned used[16];
    __shared__ short qrows[LL];
    __shared__ int qn, nsel;
    __shared__ short sel_i[KK], sel_j[KK];
    __shared__ unsigned ibits[16];

    const int b = blockIdx.x, tid = threadIdx.x;
    const int warp = tid >> 5, lane = tid & 31;
    const float* simb = &g_sim[(size_t)b * LL * LL];

    // copy lists (stride-8 global -> stride-9 smem)
#pragma unroll
    for (int q = 0; q < TL; q++) {
        int idx = tid + q * 512;                 // 0..4095
        sl[(size_t)(idx >> 3) * TLP + (idx & 7)] = g_lists[(size_t)b * LL * TL + idx];
    }
    if (tid < 16) { used[tid] = 0u; ibits[tid] = 0u; }
    if (tid == 0) { nsel = 0; qn = 0; }
    __syncthreads();
    best[tid] = sl[(size_t)tid * TLP];
    hd[tid] = 1;
    __syncthreads();

    while (true) {
        // --- phase A: mutual-best selection (thread per row) ---
        {
            const int r = tid;
            if (!((used[r >> 5] >> (r & 31)) & 1u)) {
                unsigned long long k = best[r];
                int a = (int)((k >> 9) & 511), d = (int)(k & 511);
                if (r == a && best[d] == k) {    // mutual; select once at min endpoint
                    int s = atomicAdd(&nsel, 1);
                    sel_i[s] = (short)a; sel_j[s] = (short)d;
                    atomicOr(&used[a >> 5], 1u << (a & 31));
                    atomicOr(&used[d >> 5], 1u << (d & 31));
                }
            }
            if (tid == 0) qn = 0;
        }
        __syncthreads();
        if (nsel >= KK) break;

        // --- phase B: advance dead rows via smem list; queue exhausted ---
        {
            const int r = tid;
            if (!((used[r >> 5] >> (r & 31)) & 1u)) {
                unsigned long long k = best[r];
                int a = (int)((k >> 9) & 511), d = (int)(k & 511);
                int p = a ^ d ^ r;
                if ((used[p >> 5] >> (p & 31)) & 1u) {   // cached best died
                    int h = hd[r];
                    unsigned long long nb = ~0ULL;
                    while (h < TL) {
                        unsigned long long e = sl[(size_t)r * TLP + h]; h++;
                        if (e == ~0ULL) { h = TL; break; }
                        int p2 = ((int)((e >> 9) & 511)) ^ ((int)(e & 511)) ^ r;
                        if (!((used[p2 >> 5] >> (p2 & 31)) & 1u)) { nb = e; break; }
                    }
                    hd[r] = (unsigned char)h;
                    if (nb != ~0ULL) best[r] = nb;
                    else qrows[atomicAdd(&qn, 1)] = (short)r;
                }
            }
        }
        __syncthreads();

        // --- phase C: warp-parallel rescans, REFILLING a fresh top-8 list ---
        for (int qi = warp; qi < qn; qi += 16) {
            const int r = qrows[qi];
            const float4* row4 = reinterpret_cast<const float4*>(&simb[(size_t)r * LL]);
            float4 v[4];
#pragma unroll
            for (int q = 0; q < 4; q++) v[q] = row4[lane + q * 32];
            unsigned long long keys[16];
#pragma unroll
            for (int q = 0; q < 4; q++) {
                float f[4] = {v[q].x, v[q].y, v[q].z, v[q].w};
                int cbase = (lane + q * 32) * 4;
#pragma unroll
                for (int e = 0; e < 4; e++) {
                    int cc = cbase + e;
                    unsigned long long kk = ~0ULL;
                    if (cc != r && !((used[cc >> 5] >> (cc & 31)) & 1u))
                        kk = mkkey(f[e], r, cc);
                    keys[q * 4 + e] = kk;
                }
            }
            unsigned long long m0 = 0;
#pragma unroll
            for (int t = 0; t < TL; t++) {
                unsigned long long m = ~0ULL;
#pragma unroll
                for (int q = 0; q < 16; q++) m = keys[q] < m ? keys[q] : m;
#pragma unroll
                for (int o = 16; o; o >>= 1) {
                    unsigned long long o2 = __shfl_xor_sync(0xffffffffu, m, o);
                    m = o2 < m ? o2 : m;
                }
                if (lane == 0) sl[(size_t)r * TLP + t] = m;
                if (t == 0) m0 = m;
#pragma unroll
                for (int q = 0; q < 16; q++) if (keys[q] == m) keys[q] = ~0ULL;
            }
            if (lane == 0) { best[r] = m0; hd[r] = 1; }
        }
        __syncthreads();
    }

    // --- emit kept-slot pair records (rank = position of i among sorted i's) ---
    if (tid < KK) atomicOr(&ibits[sel_i[tid] >> 5], 1u << (sel_i[tid] & 31));
    __syncthreads();
    if (tid < KK) {
        int i = sel_i[tid], j = sel_j[tid];
        int rank = 0;
        for (int w2 = 0; w2 < (i >> 5); w2++) rank += __popc(ibits[w2]);
        rank += __popc(ibits[i >> 5] & ((1u << (i & 31)) - 1u));
        float wi = g_gn[b * LL + i], wj = g_gn[b * LL + j];
        g_pairs[b * KK + rank] = make_int4(i, j, __float_as_int(wi), __float_as_int(wj));
    }
}

// =====================================================================
// K5: merge outputs — xm then sm (HBM-bound, float4 everywhere)
// =====================================================================
__global__ void __launch_bounds__(256) k_merge(const float* __restrict__ x,
                                               const float* __restrict__ src,
                                               float* __restrict__ out) {
    const int blk = blockIdx.x;
    const int b = blk >> 8, slot = blk & 255;
    int4 p = g_pairs[blk];
    const int i = p.x, j = p.y;
    const float wi = __int_as_float(p.z), wj = __int_as_float(p.w);
    const float tot = wi + wj + 1e-8f;
    const float ai = wi / tot, aj = wj / tot;
    const int t = threadIdx.x;

    const float4* xi = reinterpret_cast<const float4*>(&x[((size_t)b * LL + i) * DD]);
    const float4* xj = reinterpret_cast<const float4*>(&x[((size_t)b * LL + j) * DD]);
    float4* xo = reinterpret_cast<float4*>(&out[((size_t)b * KK + slot) * DD]);
    {
        float4 a = xi[t], c = xj[t], o;
        o.x = fmaf(ai, a.x, aj * c.x);
        o.y = fmaf(ai, a.y, aj * c.y);
        o.z = fmaf(ai, a.z, aj * c.z);
        o.w = fmaf(ai, a.w, aj * c.w);
        xo[t] = o;
    }
    const float4* si = reinterpret_cast<const float4*>(&src[((size_t)b * LL + i) * NN]);
    const float4* sj = reinterpret_cast<const float4*>(&src[((size_t)b * LL + j) * NN]);
    float4* so = reinterpret_cast<float4*>(
        &out[(size_t)BB * KK * DD + ((size_t)b * KK + slot) * NN]);
#pragma unroll
    for (int q = 0; q < 8; q++) {
        int idx = t + q * 256;
        float4 a = si[idx], c = sj[idx], o;
        o.x = a.x + c.x; o.y = a.y + c.y; o.z = a.z + c.z; o.w = a.w + c.w;
        so[idx] = o;
    }
}

// =====================================================================
extern "C" void kernel_launch(void* const* d_in, const int* in_sizes, int n_in,
                              void* d_out, int out_size) {
    const float* x = nullptr;
    const float* src = nullptr;
    const float* W = nullptr;
    for (int k = 0; k < n_in; k++) {
        if (in_sizes[k] == BB * LL * DD) x = (const float*)d_in[k];
        else if (in_sizes[k] == BB * LL * NN) src = (const float*)d_in[k];
        else if (in_sizes[k] == GD * DD) W = (const float*)d_in[k];
    }
    float* out = (float*)d_out;

    cudaFuncSetAttribute(k_greedy, cudaFuncAttributeMaxDynamicSharedMemorySize,
                         LL * TLP * (int)sizeof(unsigned long long));

    k_proj<<<(BB * LL) / 32, 128>>>(x, W);
    dim3 gsim(16, 16, BB);
    k_sim<<<gsim, 64>>>();
    k_lists<<<(BB * LL) / 8, 256>>>();
    k_greedy<<<BB, 512, LL * TLP * sizeof(unsigned long long)>>>();
    k_merge<<<BB * KK, 256>>>(x, src, out);
}

// round 5
// speedup vs baseline: 1.0979x; 1.0979x over previous
#include <cuda_runtime.h>
#include <cuda_bf16.h>

// Problem constants (fixed shapes)
#define BB 8
#define LL 512
#define DD 1024
#define NN 8192
#define GD 64
#define KK 256          // kept tokens per batch (= L - r_step, r_step = 256)
#define TL 16           // top-K candidate list length per row
#define TLP 17          // padded smem stride (bank-conflict break)

// ---------------- scratch (device globals; no allocation allowed) ----------------
__device__ float               g_gu[BB * LL * GD];     // normalized group embeddings
__device__ float               g_gn[BB * LL];          // raw norms (merge weights)
__device__ float               g_sim[BB * LL * LL];    // full sim matrix per batch
__device__ unsigned long long  g_lists[BB * LL * TL];  // per-row top-16 keys
__device__ int4                g_pairs[BB * KK];       // {i, j, bits(wi), bits(wj)} per kept slot

// float -> totally-ordered ascending unsigned
__device__ __forceinline__ unsigned ordf(float f) {
    unsigned u = __float_as_uint(f);
    return (u & 0x80000000u) ? ~u : (u | 0x80000000u);
}

// build key: ascending key == descending sim, tie-break (i,j) lexicographic
__device__ __forceinline__ unsigned long long mkkey(float s, int r, int cc) {
    int a = min(r, cc), d = max(r, cc);
    return ((unsigned long long)(~ordf(s)) << 18) | (unsigned)((a << 9) | d);
}

// =====================================================================
// K1: g = x @ W^T, then gn, gu. 128 blocks x 128 thr.
// Thread tile 4 rows x 4 cols; broadcast-friendly smem loads.
// =====================================================================
__global__ void __launch_bounds__(128) k_proj(const float* __restrict__ x,
                                              const float* __restrict__ W) {
    __shared__ float xs[32][65];
    __shared__ float ws[64][65];
    __shared__ float rowsq[32][17];
    __shared__ float inv_s[32];

    const int tid = threadIdx.x;
    const int rowBase = blockIdx.x * 32;
    const int rg = tid & 7, cg = tid >> 3;          // 8 x 16
    const int r0 = rg * 4, c0 = cg * 4;

    float acc[4][4];
#pragma unroll
    for (int u = 0; u < 4; u++)
#pragma unroll
        for (int v = 0; v < 4; v++) acc[u][v] = 0.f;

    for (int kc = 0; kc < DD; kc += 64) {
#pragma unroll
        for (int it = 0; it < 4; it++) {            // xs: 512 float4
            int idx = tid + it * 128;
            int rr = idx >> 4, kk = (idx & 15) << 2;
            float4 v = *reinterpret_cast<const float4*>(
                &x[(size_t)(rowBase + rr) * DD + kc + kk]);
            xs[rr][kk] = v.x; xs[rr][kk + 1] = v.y; xs[rr][kk + 2] = v.z; xs[rr][kk + 3] = v.w;
        }
#pragma unroll
        for (int it = 0; it < 8; it++) {            // ws: 1024 float4
            int idx = tid + it * 128;
            int rr = idx >> 4, kk = (idx & 15) << 2;
            float4 v = *reinterpret_cast<const float4*>(
                &W[(size_t)rr * DD + kc + kk]);
            ws[rr][kk] = v.x; ws[rr][kk + 1] = v.y; ws[rr][kk + 2] = v.z; ws[rr][kk + 3] = v.w;
        }
        __syncthreads();
#pragma unroll 4
        for (int k = 0; k < 64; k++) {
            float a[4], bv[4];
#pragma unroll
            for (int u = 0; u < 4; u++) a[u] = xs[r0 + u][k];
#pragma unroll
            for (int v = 0; v < 4; v++) bv[v] = ws[c0 + v][k];
#pragma unroll
            for (int u = 0; u < 4; u++)
#pragma unroll
                for (int v = 0; v < 4; v++)
                    acc[u][v] = fmaf(a[u], bv[v], acc[u][v]);
        }
        __syncthreads();
    }
    // row norms
#pragma unroll
    for (int u = 0; u < 4; u++) {
        float s = 0.f;
#pragma unroll
        for (int v = 0; v < 4; v++) s = fmaf(acc[u][v], acc[u][v], s);
        rowsq[r0 + u][cg] = s;
    }
    __syncthreads();
    if (tid < 32) {
        float s = 0.f;
#pragma unroll
        for (int c = 0; c < 16; c++) s += rowsq[tid][c];
        float m = sqrtf(s);
        g_gn[rowBase + tid] = m;
        inv_s[tid] = 1.f / fmaxf(m, 1e-12f);
    }
    __syncthreads();
#pragma unroll
    for (int u = 0; u < 4; u++) {
        float iv = inv_s[r0 + u];
        float4 o;
        o.x = acc[u][0] * iv; o.y = acc[u][1] * iv;
        o.z = acc[u][2] * iv; o.w = acc[u][3] * iv;
        *reinterpret_cast<float4*>(&g_gu[(size_t)(rowBase + r0 + u) * GD + c0]) = o;
    }
}

// =====================================================================
// K2: sim = gu @ gu^T; 32x32 tiles, 64 threads, thread = 4x4.
// sim bitwise symmetric (same k-order both sides) — required.
// =====================================================================
__global__ void __launch_bounds__(64) k_sim() {
    __shared__ float A[32][65], Bm[32][65];
    const int b = blockIdx.z, i0 = blockIdx.y * 32, j0 = blockIdx.x * 32;
    const int tid = threadIdx.x;
#pragma unroll
    for (int it = 0; it < 8; it++) {                // each tile 512 float4
        int idx = tid + it * 64;
        int rr = idx >> 4, kk = (idx & 15) << 2;
        float4 v = *reinterpret_cast<const float4*>(
            &g_gu[((size_t)b * LL + i0 + rr) * GD + kk]);
        A[rr][kk] = v.x; A[rr][kk + 1] = v.y; A[rr][kk + 2] = v.z; A[rr][kk + 3] = v.w;
        float4 w = *reinterpret_cast<const float4*>(
            &g_gu[((size_t)b * LL + j0 + rr) * GD + kk]);
        Bm[rr][kk] = w.x; Bm[rr][kk + 1] = w.y; Bm[rr][kk + 2] = w.z; Bm[rr][kk + 3] = w.w;
    }
    __syncthreads();
    const int rg = tid & 7, cg = tid >> 3;          // 8 x 8
    const int r0 = rg * 4, c0 = cg * 4;
    float acc[4][4];
#pragma unroll
    for (int u = 0; u < 4; u++)
#pragma unroll
        for (int v = 0; v < 4; v++) acc[u][v] = 0.f;
#pragma unroll 8
    for (int k = 0; k < GD; k++) {
        float a[4], bv[4];
#pragma unroll
        for (int u = 0; u < 4; u++) a[u] = A[r0 + u][k];
#pragma unroll
        for (int v = 0; v < 4; v++) bv[v] = Bm[c0 + v][k];
#pragma unroll
        for (int u = 0; u < 4; u++)
#pragma unroll
            for (int v = 0; v < 4; v++)
                acc[u][v] = fmaf(a[u], bv[v], acc[u][v]);
    }
#pragma unroll
    for (int u = 0; u < 4; u++) {
        float4 o;
        o.x = acc[u][0]; o.y = acc[u][1]; o.z = acc[u][2]; o.w = acc[u][3];
        *reinterpret_cast<float4*>(
            &g_sim[((size_t)b * LL + i0 + r0 + u) * LL + j0 + c0]) = o;
    }
}

// =====================================================================
// K3: per-row top-16 candidate keys (ascending). Warp per row.
// =====================================================================
__global__ void __launch_bounds__(256) k_lists() {
    const int warp = threadIdx.x >> 5, lane = threadIdx.x & 31;
    const int rr = blockIdx.x * 8 + warp;      // 0..4095 flattened
    const int r = rr & (LL - 1);
    const float4* row4 = reinterpret_cast<const float4*>(&g_sim[(size_t)rr * LL]);
    unsigned long long keys[16];
#pragma unroll
    for (int q = 0; q < 4; q++) {
        float4 v = row4[lane + q * 32];
        float f[4] = {v.x, v.y, v.z, v.w};
        int cbase = (lane + q * 32) * 4;
#pragma unroll
        for (int e = 0; e < 4; e++) {
            int cc = cbase + e;
            keys[q * 4 + e] = (cc == r) ? ~0ULL : mkkey(f[e], r, cc);
        }
    }
    unsigned long long* out = &g_lists[(size_t)rr * TL];
    for (int t = 0; t < TL; t++) {
        unsigned long long m = ~0ULL;
#pragma unroll
        for (int q = 0; q < 16; q++) m = keys[q] < m ? keys[q] : m;
#pragma unroll
        for (int o = 16; o; o >>= 1) {
            unsigned long long o2 = __shfl_xor_sync(0xffffffffu, m, o);
            m = o2 < m ? o2 : m;
        }
        if (lane == 0) out[t] = m;
#pragma unroll
        for (int q = 0; q < 16; q++) if (keys[q] == m) keys[q] = ~0ULL;
    }
}

// =====================================================================
// K4: greedy matching via iterated mutual-best rounds with smem top-16
// lists (R3-measured configuration). Selected set identical to
// sequential greedy (distinct keys, lists hold true global top-16).
// =====================================================================
__global__ void __launch_bounds__(512) k_greedy() {
    extern __shared__ unsigned long long sl[];   // LL*TLP keys (69.6 KB)
    __shared__ unsigned long long best[LL];
    __shared__ unsigned char hd[LL];
    __shared__ unsigned used[16];
    __shared__ short qrows[LL];
    __shared__ int qn, nsel;
    __shared__ short sel_i[KK], sel_j[KK];
    __shared__ unsigned ibits[16];

    const int b = blockIdx.x, tid = threadIdx.x;
    const int warp = tid >> 5, lane = tid & 31;
    const float* simb = &g_sim[(size_t)b * LL * LL];

    // copy lists (stride-16 global -> stride-17 smem)
#pragma unroll
    for (int q = 0; q < TL; q++) {
        int idx = tid + q * 512;                 // 0..8191
        sl[(size_t)(idx >> 4) * TLP + (idx & 15)] = g_lists[(size_t)b * LL * TL + idx];
    }
    if (tid < 16) { used[tid] = 0u; ibits[tid] = 0u; }
    if (tid == 0) { nsel = 0; qn = 0; }
    __syncthreads();
    best[tid] = sl[(size_t)tid * TLP];
    hd[tid] = 1;
    __syncthreads();

    while (true) {
        // --- phase A: mutual-best selection (thread per row) ---
        {
            const int r = tid;
            if (!((used[r >> 5] >> (r & 31)) & 1u)) {
                unsigned long long k = best[r];
                int a = (int)((k >> 9) & 511), d = (int)(k & 511);
                if (r == a && best[d] == k) {    // mutual; select once at min endpoint
                    int s = atomicAdd(&nsel, 1);
                    sel_i[s] = (short)a; sel_j[s] = (short)d;
                    atomicOr(&used[a >> 5], 1u << (a & 31));
                    atomicOr(&used[d >> 5], 1u << (d & 31));
                }
            }
            if (tid == 0) qn = 0;
        }
        __syncthreads();
        if (nsel >= KK) break;

        // --- phase B: advance dead rows via smem list; queue exhausted ---
        {
            const int r = tid;
            if (!((used[r >> 5] >> (r & 31)) & 1u)) {
                unsigned long long k = best[r];
                int a = (int)((k >> 9) & 511), d = (int)(k & 511);
                int p = a ^ d ^ r;
                if ((used[p >> 5] >> (p & 31)) & 1u) {   // cached best died
                    int h = hd[r];
                    unsigned long long nb = ~0ULL;
                    while (h < TL) {
                        unsigned long long e = sl[(size_t)r * TLP + h]; h++;
                        int p2 = ((int)((e >> 9) & 511)) ^ ((int)(e & 511)) ^ r;
                        if (!((used[p2 >> 5] >> (p2 & 31)) & 1u)) { nb = e; break; }
                    }
                    hd[r] = (unsigned char)h;
                    if (nb != ~0ULL) best[r] = nb;
                    else qrows[atomicAdd(&qn, 1)] = (short)r;
                }
            }
        }
        __syncthreads();

        // --- phase C: warp-parallel full rescans (L2-resident rows) ---
        for (int qi = warp; qi < qn; qi += 16) {
            const int r = qrows[qi];
            const float4* row4 = reinterpret_cast<const float4*>(&simb[(size_t)r * LL]);
            float4 v[4];
#pragma unroll
            for (int q = 0; q < 4; q++) v[q] = row4[lane + q * 32];
            unsigned long long m = ~0ULL;
#pragma unroll
            for (int q = 0; q < 4; q++) {
                float f[4] = {v[q].x, v[q].y, v[q].z, v[q].w};
                int cbase = (lane + q * 32) * 4;
#pragma unroll
                for (int e = 0; e < 4; e++) {
                    int cc = cbase + e;
                    if (cc == r) continue;
                    if ((used[cc >> 5] >> (cc & 31)) & 1u) continue;
                    unsigned long long kk = mkkey(f[e], r, cc);
                    m = kk < m ? kk : m;
                }
            }
#pragma unroll
            for (int o = 16; o; o >>= 1) {
                unsigned long long o2 = __shfl_xor_sync(0xffffffffu, m, o);
                m = o2 < m ? o2 : m;
            }
            if (lane == 0) best[r] = m;
        }
        __syncthreads();
    }

    // --- emit kept-slot pair records (rank = position of i among sorted i's) ---
    if (tid < KK) atomicOr(&ibits[sel_i[tid] >> 5], 1u << (sel_i[tid] & 31));
    __syncthreads();
    if (tid < KK) {
        int i = sel_i[tid], j = sel_j[tid];
        int rank = 0;
        for (int w2 = 0; w2 < (i >> 5); w2++) rank += __popc(ibits[w2]);
        rank += __popc(ibits[i >> 5] & ((1u << (i & 31)) - 1u));
        float wi = g_gn[b * LL + i], wj = g_gn[b * LL + j];
        g_pairs[b * KK + rank] = make_int4(i, j, __float_as_int(wi), __float_as_int(wj));
    }
}

// =====================================================================
// K5: merge outputs — xm then sm (HBM-bound, float4 everywhere)
// =====================================================================
__global__ void __launch_bounds__(256) k_merge(const float* __restrict__ x,
                                               const float* __restrict__ src,
                                               float* __restrict__ out) {
    const int blk = blockIdx.x;
    const int b = blk >> 8, slot = blk & 255;
    int4 p = g_pairs[blk];
    const int i = p.x, j = p.y;
    const float wi = __int_as_float(p.z), wj = __int_as_float(p.w);
    const float tot = wi + wj + 1e-8f;
    const float ai = wi / tot, aj = wj / tot;
    const int t = threadIdx.x;

    const float4* xi = reinterpret_cast<const float4*>(&x[((size_t)b * LL + i) * DD]);
    const float4* xj = reinterpret_cast<const float4*>(&x[((size_t)b * LL + j) * DD]);
    float4* xo = reinterpret_cast<float4*>(&out[((size_t)b * KK + slot) * DD]);
    {
        float4 a = xi[t], c = xj[t], o;
        o.x = fmaf(ai, a.x, aj * c.x);
        o.y = fmaf(ai, a.y, aj * c.y);
        o.z = fmaf(ai, a.z, aj * c.z);
        o.w = fmaf(ai, a.w, aj * c.w);
        xo[t] = o;
    }
    const float4* si = reinterpret_cast<const float4*>(&src[((size_t)b * LL + i) * NN]);
    const float4* sj = reinterpret_cast<const float4*>(&src[((size_t)b * LL + j) * NN]);
    float4* so = reinterpret_cast<float4*>(
        &out[(size_t)BB * KK * DD + ((size_t)b * KK + slot) * NN]);
#pragma unroll
    for (int q = 0; q < 8; q++) {
        int idx = t + q * 256;
        float4 a = si[idx], c = sj[idx], o;
        o.x = a.x + c.x; o.y = a.y + c.y; o.z = a.z + c.z; o.w = a.w + c.w;
        so[idx] = o;
    }
}

// =====================================================================
extern "C" void kernel_launch(void* const* d_in, const int* in_sizes, int n_in,
                              void* d_out, int out_size) {
    const float* x = nullptr;
    const float* src = nullptr;
    const float* W = nullptr;
    for (int k = 0; k < n_in; k++) {
        if (in_sizes[k] == BB * LL * DD) x = (const float*)d_in[k];
        else if (in_sizes[k] == BB * LL * NN) src = (const float*)d_in[k];
        else if (in_sizes[k] == GD * DD) W = (const float*)d_in[k];
    }
    float* out = (float*)d_out;

    cudaFuncSetAttribute(k_greedy, cudaFuncAttributeMaxDynamicSharedMemorySize,
                         LL * TLP * (int)sizeof(unsigned long long));

    k_proj<<<(BB * LL) / 32, 128>>>(x, W);
    dim3 gsim(16, 16, BB);
    k_sim<<<gsim, 64>>>();
    k_lists<<<(BB * LL) / 8, 256>>>();
    k_greedy<<<BB, 512, LL * TLP * sizeof(unsigned long long)>>>();
    k_merge<<<BB * KK, 256>>>(x, src, out);
}

// round 10
// speedup vs baseline: 1.1422x; 1.0403x over previous
#include <cuda_runtime.h>
#include <cuda_bf16.h>

// Problem constants (fixed shapes)
#define BB 8
#define LL 512
#define DD 1024
#define NN 8192
#define GD 64
#define KK 256          // kept tokens per batch (= L - r_step, r_step = 256)
#define TL 16           // top-K candidate list length per row
#define TLP 17          // padded smem stride (bank-conflict break)
#define RFN 8           // refill depth on phase-C rescan

// ---------------- scratch (device globals; no allocation allowed) ----------------
__device__ float               g_gu[BB * LL * GD];     // normalized group embeddings
__device__ float               g_gn[BB * LL];          // raw norms (merge weights)
__device__ float               g_sim[BB * LL * LL];    // full sim matrix per batch
__device__ unsigned long long  g_lists[BB * LL * TL];  // per-row top-16 keys
__device__ int4                g_pairs[BB * KK];       // {i, j, bits(wi), bits(wj)} per kept slot

// float -> totally-ordered ascending unsigned
__device__ __forceinline__ unsigned ordf(float f) {
    unsigned u = __float_as_uint(f);
    return (u & 0x80000000u) ? ~u : (u | 0x80000000u);
}

// full pair key: ascending == descending sim, tie-break (i,j) lexicographic
__device__ __forceinline__ unsigned long long keyfrom(unsigned simkey, int r, int cc) {
    int a = min(r, cc), d = max(r, cc);
    return ((unsigned long long)simkey << 18) | (unsigned)((a << 9) | d);
}

// =====================================================================
// K1: g = x @ W^T, then gn, gu. 128 blocks x 128 thr, thread tile 4x4.
// =====================================================================
__global__ void __launch_bounds__(128) k_proj(const float* __restrict__ x,
                                              const float* __restrict__ W) {
    __shared__ float xs[32][65];
    __shared__ float ws[64][65];
    __shared__ float rowsq[32][17];
    __shared__ float inv_s[32];

    const int tid = threadIdx.x;
    const int rowBase = blockIdx.x * 32;
    const int rg = tid & 7, cg = tid >> 3;          // 8 x 16
    const int r0 = rg * 4, c0 = cg * 4;

    float acc[4][4];
#pragma unroll
    for (int u = 0; u < 4; u++)
#pragma unroll
        for (int v = 0; v < 4; v++) acc[u][v] = 0.f;

    for (int kc = 0; kc < DD; kc += 64) {
#pragma unroll
        for (int it = 0; it < 4; it++) {            // xs: 512 float4
            int idx = tid + it * 128;
            int rr = idx >> 4, kk = (idx & 15) << 2;
            float4 v = *reinterpret_cast<const float4*>(
                &x[(size_t)(rowBase + rr) * DD + kc + kk]);
            xs[rr][kk] = v.x; xs[rr][kk + 1] = v.y; xs[rr][kk + 2] = v.z; xs[rr][kk + 3] = v.w;
        }
#pragma unroll
        for (int it = 0; it < 8; it++) {            // ws: 1024 float4
            int idx = tid + it * 128;
            int rr = idx >> 4, kk = (idx & 15) << 2;
            float4 v = *reinterpret_cast<const float4*>(
                &W[(size_t)rr * DD + kc + kk]);
            ws[rr][kk] = v.x; ws[rr][kk + 1] = v.y; ws[rr][kk + 2] = v.z; ws[rr][kk + 3] = v.w;
        }
        __syncthreads();
#pragma unroll 4
        for (int k = 0; k < 64; k++) {
            float a[4], bv[4];
#pragma unroll
            for (int u = 0; u < 4; u++) a[u] = xs[r0 + u][k];
#pragma unroll
            for (int v = 0; v < 4; v++) bv[v] = ws[c0 + v][k];
#pragma unroll
            for (int u = 0; u < 4; u++)
#pragma unroll
                for (int v = 0; v < 4; v++)
                    acc[u][v] = fmaf(a[u], bv[v], acc[u][v]);
        }
        __syncthreads();
    }
#pragma unroll
    for (int u = 0; u < 4; u++) {
        float s = 0.f;
#pragma unroll
        for (int v = 0; v < 4; v++) s = fmaf(acc[u][v], acc[u][v], s);
        rowsq[r0 + u][cg] = s;
    }
    __syncthreads();
    if (tid < 32) {
        float s = 0.f;
#pragma unroll
        for (int c = 0; c < 16; c++) s += rowsq[tid][c];
        float m = sqrtf(s);
        g_gn[rowBase + tid] = m;
        inv_s[tid] = 1.f / fmaxf(m, 1e-12f);
    }
    __syncthreads();
#pragma unroll
    for (int u = 0; u < 4; u++) {
        float iv = inv_s[r0 + u];
        float4 o;
        o.x = acc[u][0] * iv; o.y = acc[u][1] * iv;
        o.z = acc[u][2] * iv; o.w = acc[u][3] * iv;
        *reinterpret_cast<float4*>(&g_gu[(size_t)(rowBase + r0 + u) * GD + c0]) = o;
    }
}

// =====================================================================
// K2: sim = gu @ gu^T; 32x32 tiles, 64 threads, thread = 4x4.
// sim bitwise symmetric (same k-order both sides) — required.
// =====================================================================
__global__ void __launch_bounds__(64) k_sim() {
    __shared__ float A[32][65], Bm[32][65];
    const int b = blockIdx.z, i0 = blockIdx.y * 32, j0 = blockIdx.x * 32;
    const int tid = threadIdx.x;
#pragma unroll
    for (int it = 0; it < 8; it++) {
        int idx = tid + it * 64;
        int rr = idx >> 4, kk = (idx & 15) << 2;
        float4 v = *reinterpret_cast<const float4*>(
            &g_gu[((size_t)b * LL + i0 + rr) * GD + kk]);
        A[rr][kk] = v.x; A[rr][kk + 1] = v.y; A[rr][kk + 2] = v.z; A[rr][kk + 3] = v.w;
        float4 w = *reinterpret_cast<const float4*>(
            &g_gu[((size_t)b * LL + j0 + rr) * GD + kk]);
        Bm[rr][kk] = w.x; Bm[rr][kk + 1] = w.y; Bm[rr][kk + 2] = w.z; Bm[rr][kk + 3] = w.w;
    }
    __syncthreads();
    const int rg = tid & 7, cg = tid >> 3;
    const int r0 = rg * 4, c0 = cg * 4;
    float acc[4][4];
#pragma unroll
    for (int u = 0; u < 4; u++)
#pragma unroll
        for (int v = 0; v < 4; v++) acc[u][v] = 0.f;
#pragma unroll 8
    for (int k = 0; k < GD; k++) {
        float a[4], bv[4];
#pragma unroll
        for (int u = 0; u < 4; u++) a[u] = A[r0 + u][k];
#pragma unroll
        for (int v = 0; v < 4; v++) bv[v] = Bm[c0 + v][k];
#pragma unroll
        for (int u = 0; u < 4; u++)
#pragma unroll
            for (int v = 0; v < 4; v++)
                acc[u][v] = fmaf(a[u], bv[v], acc[u][v]);
    }
#pragma unroll
    for (int u = 0; u < 4; u++) {
        float4 o;
        o.x = acc[u][0]; o.y = acc[u][1]; o.z = acc[u][2]; o.w = acc[u][3];
        *reinterpret_cast<float4*>(
            &g_sim[((size_t)b * LL + i0 + r0 + u) * LL + j0 + c0]) = o;
    }
}

// =====================================================================
// K3: per-row top-16 candidate keys via REDUX-based selection.
// Within a row, full-key order == (simkey asc, then column asc) —
// resolved with two u32 __reduce_min_sync ops. Bitwise-identical lists.
// =====================================================================
__global__ void __launch_bounds__(256) k_lists() {
    const int warp = threadIdx.x >> 5, lane = threadIdx.x & 31;
    const int rr = blockIdx.x * 8 + warp;      // 0..4095 flattened
    const int r = rr & (LL - 1);
    const float4* row4 = reinterpret_cast<const float4*>(&g_sim[(size_t)rr * LL]);
    unsigned sk[16];
#pragma unroll
    for (int q = 0; q < 4; q++) {
        float4 v = row4[lane + q * 32];
        float f[4] = {v.x, v.y, v.z, v.w};
        int cbase = (lane + q * 32) * 4;
#pragma unroll
        for (int e = 0; e < 4; e++) {
            int cc = cbase + e;
            sk[q * 4 + e] = (cc == r) ? 0xFFFFFFFFu : ~ordf(f[e]);
        }
    }
    unsigned long long* out = &g_lists[(size_t)rr * TL];
    for (int t = 0; t < TL; t++) {
        unsigned lm = 0xFFFFFFFFu; int le = 0;
#pragma unroll
        for (int s = 0; s < 16; s++) if (sk[s] < lm) { lm = sk[s]; le = s; }
        unsigned m = __reduce_min_sync(0xffffffffu, lm);
        int lcc = (lane + (le >> 2) * 32) * 4 + (le & 3);
        unsigned cprop = (lm == m) ? (unsigned)lcc : 0xFFFFu;
        unsigned cmin = __reduce_min_sync(0xffffffffu, cprop);
        if (lm == m && (unsigned)lcc == cmin) sk[le] = 0xFFFFFFFFu;
        if (lane == 0) out[t] = keyfrom(m, r, (int)cmin);
    }
}

// =====================================================================
// K4: greedy matching via iterated mutual-best rounds, smem top-16
// lists, REDUX phase-C rescans that REFILL top-8. Selected set is
// identical to sequential greedy.
// =====================================================================
__global__ void __launch_bounds__(512) k_greedy() {
    extern __shared__ unsigned long long sl[];   // LL*TLP keys (69.6 KB)
    __shared__ unsigned long long best[LL];
    __shared__ unsigned char hd[LL];
    __shared__ unsigned char lstn[LL];
    __shared__ unsigned used[16];
    __shared__ short qrows[LL];
    __shared__ int qn, nsel;
    __shared__ short sel_i[KK], sel_j[KK];
    __shared__ unsigned ibits[16];

    const int b = blockIdx.x, tid = threadIdx.x;
    const int warp = tid >> 5, lane = tid & 31;
    const float* simb = &g_sim[(size_t)b * LL * LL];

    // copy lists (stride-16 global -> stride-17 smem)
#pragma unroll
    for (int q = 0; q < TL; q++) {
        int idx = tid + q * 512;                 // 0..8191
        sl[(size_t)(idx >> 4) * TLP + (idx & 15)] = g_lists[(size_t)b * LL * TL + idx];
    }
    if (tid < 16) { used[tid] = 0u; ibits[tid] = 0u; }
    if (tid == 0) { nsel = 0; qn = 0; }
    __syncthreads();
    best[tid] = sl[(size_t)tid * TLP];
    hd[tid] = 1;
    lstn[tid] = TL;
    __syncthreads();

    while (true) {
        // --- phase A: mutual-best selection (thread per row) ---
        {
            const int r = tid;
            if (!((used[r >> 5] >> (r & 31)) & 1u)) {
                unsigned long long k = best[r];
                int a = (int)((k >> 9) & 511), d = (int)(k & 511);
                if (r == a && best[d] == k) {    // mutual; select once at min endpoint
                    int s = atomicAdd(&nsel, 1);
                    sel_i[s] = (short)a; sel_j[s] = (short)d;
                    atomicOr(&used[a >> 5], 1u << (a & 31));
                    atomicOr(&used[d >> 5], 1u << (d & 31));
                }
            }
            if (tid == 0) qn = 0;
        }
        __syncthreads();
        if (nsel >= KK) break;

        // --- phase B: advance dead rows via smem list; queue exhausted ---
        {
            const int r = tid;
            if (!((used[r >> 5] >> (r & 31)) & 1u)) {
                unsigned long long k = best[r];
                int a = (int)((k >> 9) & 511), d = (int)(k & 511);
                int p = a ^ d ^ r;
                if ((used[p >> 5] >> (p & 31)) & 1u) {   // cached best died
                    int h = hd[r];
                    const int cap = lstn[r];
                    unsigned long long nb = ~0ULL;
                    while (h < cap) {
                        unsigned long long e = sl[(size_t)r * TLP + h]; h++;
                        if (e == ~0ULL) { h = cap; break; }
                        int p2 = ((int)((e >> 9) & 511)) ^ ((int)(e & 511)) ^ r;
                        if (!((used[p2 >> 5] >> (p2 & 31)) & 1u)) { nb = e; break; }
                    }
                    hd[r] = (unsigned char)h;
                    if (nb != ~0ULL) best[r] = nb;
                    else qrows[atomicAdd(&qn, 1)] = (short)r;
                }
            }
        }
        __syncthreads();

        // --- phase C: warp-parallel rescans, refilling fresh top-8 ---
        for (int qi = warp; qi < qn; qi += 16) {
            const int r = qrows[qi];
            const float4* row4 = reinterpret_cast<const float4*>(&simb[(size_t)r * LL]);
            float4 v[4];
#pragma unroll
            for (int q = 0; q < 4; q++) v[q] = row4[lane + q * 32];
            unsigned sk[16];
#pragma unroll
            for (int q = 0; q < 4; q++) {
                float f[4] = {v[q].x, v[q].y, v[q].z, v[q].w};
                int cbase = (lane + q * 32) * 4;
#pragma unroll
                for (int e = 0; e < 4; e++) {
                    int cc = cbase + e;
                    unsigned kk = 0xFFFFFFFFu;
                    if (cc != r && !((used[cc >> 5] >> (cc & 31)) & 1u))
                        kk = ~ordf(f[e]);
                    sk[q * 4 + e] = kk;
                }
            }
            unsigned long long first = ~0ULL;
#pragma unroll
            for (int t = 0; t < RFN; t++) {
                unsigned lm = 0xFFFFFFFFu; int le = 0;
#pragma unroll
                for (int s = 0; s < 16; s++) if (sk[s] < lm) { lm = sk[s]; le = s; }
                unsigned m = __reduce_min_sync(0xffffffffu, lm);
                int lcc = (lane + (le >> 2) * 32) * 4 + (le & 3);
                unsigned cprop = (lm == m) ? (unsigned)lcc : 0xFFFFu;
                unsigned cmin = __reduce_min_sync(0xffffffffu, cprop);
                if (lm == m && (unsigned)lcc == cmin) sk[le] = 0xFFFFFFFFu;
                unsigned long long key = ~0ULL;
                if (m != 0xFFFFFFFFu) key = keyfrom(m, r, (int)cmin);
                if (lane == 0) sl[(size_t)r * TLP + t] = key;
                if (t == 0) first = key;
            }
            if (lane == 0) { best[r] = first; hd[r] = 1; lstn[r] = RFN; }
        }
        __syncthreads();
    }

    // --- emit kept-slot pair records (rank = position of i among sorted i's) ---
    if (tid < KK) atomicOr(&ibits[sel_i[tid] >> 5], 1u << (sel_i[tid] & 31));
    __syncthreads();
    if (tid < KK) {
        int i = sel_i[tid], j = sel_j[tid];
        int rank = 0;
        for (int w2 = 0; w2 < (i >> 5); w2++) rank += __popc(ibits[w2]);
        rank += __popc(ibits[i >> 5] & ((1u << (i & 31)) - 1u));
        float wi = g_gn[b * LL + i], wj = g_gn[b * LL + j];
        g_pairs[b * KK + rank] = make_int4(i, j, __float_as_int(wi), __float_as_int(wj));
    }
}

// =====================================================================
// K5: merge outputs — streaming loads/stores (data touched exactly once)
// =====================================================================
__global__ void __launch_bounds__(256) k_merge(const float* __restrict__ x,
                                               const float* __restrict__ src,
                                               float* __restrict__ out) {
    const int blk = blockIdx.x;
    const int b = blk >> 8, slot = blk & 255;
    int4 p = g_pairs[blk];
    const int i = p.x, j = p.y;
    const float wi = __int_as_float(p.z), wj = __int_as_float(p.w);
    const float tot = wi + wj + 1e-8f;
    const float ai = wi / tot, aj = wj / tot;
    const int t = threadIdx.x;

    const float4* xi = reinterpret_cast<const float4*>(&x[((size_t)b * LL + i) * DD]);
    const float4* xj = reinterpret_cast<const float4*>(&x[((size_t)b * LL + j) * DD]);
    float4* xo = reinterpret_cast<float4*>(&out[((size_t)b * KK + slot) * DD]);
    {
        float4 a = __ldcs(&xi[t]), c = __ldcs(&xj[t]), o;
        o.x = fmaf(ai, a.x, aj * c.x);
        o.y = fmaf(ai, a.y, aj * c.y);
        o.z = fmaf(ai, a.z, aj * c.z);
        o.w = fmaf(ai, a.w, aj * c.w);
        __stcs(&xo[t], o);
    }
    const float4* si = reinterpret_cast<const float4*>(&src[((size_t)b * LL + i) * NN]);
    const float4* sj = reinterpret_cast<const float4*>(&src[((size_t)b * LL + j) * NN]);
    float4* so = reinterpret_cast<float4*>(
        &out[(size_t)BB * KK * DD + ((size_t)b * KK + slot) * NN]);
#pragma unroll
    for (int q = 0; q < 8; q++) {
        int idx = t + q * 256;
        float4 a = __ldcs(&si[idx]), c = __ldcs(&sj[idx]), o;
        o.x = a.x + c.x; o.y = a.y + c.y; o.z = a.z + c.z; o.w = a.w + c.w;
        __stcs(&so[idx], o);
    }
}

// =====================================================================
extern "C" void kernel_launch(void* const* d_in, const int* in_sizes, int n_in,
                              void* d_out, int out_size) {
    const float* x = nullptr;
    const float* src = nullptr;
    const float* W = nullptr;
    for (int k = 0; k < n_in; k++) {
        if (in_sizes[k] == BB * LL * DD) x = (const float*)d_in[k];
        else if (in_sizes[k] == BB * LL * NN) src = (const float*)d_in[k];
        else if (in_sizes[k] == GD * DD) W = (const float*)d_in[k];
    }
    float* out = (float*)d_out;

    cudaFuncSetAttribute(k_greedy, cudaFuncAttributeMaxDynamicSharedMemorySize,
                         LL * TLP * (int)sizeof(unsigned long long));

    k_proj<<<(BB * LL) / 32, 128>>>(x, W);
    dim3 gsim(16, 16, BB);
    k_sim<<<gsim, 64>>>();
    k_lists<<<(BB * LL) / 8, 256>>>();
    k_greedy<<<BB, 512, LL * TLP * sizeof(unsigned long long)>>>();
    k_merge<<<BB * KK, 256>>>(x, src, out);
}

// round 11
// speedup vs baseline: 1.2461x; 1.0910x over previous
#include <cuda_runtime.h>
#include <cuda_bf16.h>

// Problem constants (fixed shapes)
#define BB 8
#define LL 512
#define DD 1024
#define NN 8192
#define GD 64
#define KK 256          // kept tokens per batch (= L - r_step, r_step = 256)
#define TL 16           // top-K candidate list length per row
#define TLP 17          // padded smem stride (bank-conflict break)

// ---------------- scratch (device globals; no allocation allowed) ----------------
__device__ float               g_gu[BB * LL * GD];     // normalized group embeddings
__device__ float               g_gn[BB * LL];          // raw norms (merge weights)
__device__ float               g_sim[BB * LL * LL];    // full sim matrix per batch
__device__ unsigned long long  g_lists[BB * LL * TL];  // per-row top-16 keys
__device__ int4                g_pairs[BB * KK];       // {i, j, bits(wi), bits(wj)} per kept slot

// float -> totally-ordered ascending unsigned
__device__ __forceinline__ unsigned ordf(float f) {
    unsigned u = __float_as_uint(f);
    return (u & 0x80000000u) ? ~u : (u | 0x80000000u);
}

// full pair key: ascending == descending sim, tie-break (i,j) lexicographic
__device__ __forceinline__ unsigned long long keyfrom(unsigned simkey, int r, int cc) {
    int a = min(r, cc), d = max(r, cc);
    return ((unsigned long long)simkey << 18) | (unsigned)((a << 9) | d);
}

// =====================================================================
// K1: g = x @ W^T, then gn, gu. 128 blocks x 128 thr, thread tile 4x4.
// =====================================================================
__global__ void __launch_bounds__(128) k_proj(const float* __restrict__ x,
                                              const float* __restrict__ W) {
    __shared__ float xs[32][65];
    __shared__ float ws[64][65];
    __shared__ float rowsq[32][17];
    __shared__ float inv_s[32];

    const int tid = threadIdx.x;
    const int rowBase = blockIdx.x * 32;
    const int rg = tid & 7, cg = tid >> 3;          // 8 x 16
    const int r0 = rg * 4, c0 = cg * 4;

    float acc[4][4];
#pragma unroll
    for (int u = 0; u < 4; u++)
#pragma unroll
        for (int v = 0; v < 4; v++) acc[u][v] = 0.f;

    for (int kc = 0; kc < DD; kc += 64) {
#pragma unroll
        for (int it = 0; it < 4; it++) {            // xs: 512 float4
            int idx = tid + it * 128;
            int rr = idx >> 4, kk = (idx & 15) << 2;
            float4 v = *reinterpret_cast<const float4*>(
                &x[(size_t)(rowBase + rr) * DD + kc + kk]);
            xs[rr][kk] = v.x; xs[rr][kk + 1] = v.y; xs[rr][kk + 2] = v.z; xs[rr][kk + 3] = v.w;
        }
#pragma unroll
        for (int it = 0; it < 8; it++) {            // ws: 1024 float4
            int idx = tid + it * 128;
            int rr = idx >> 4, kk = (idx & 15) << 2;
            float4 v = *reinterpret_cast<const float4*>(
                &W[(size_t)rr * DD + kc + kk]);
            ws[rr][kk] = v.x; ws[rr][kk + 1] = v.y; ws[rr][kk + 2] = v.z; ws[rr][kk + 3] = v.w;
        }
        __syncthreads();
#pragma unroll 4
        for (int k = 0; k < 64; k++) {
            float a[4], bv[4];
#pragma unroll
            for (int u = 0; u < 4; u++) a[u] = xs[r0 + u][k];
#pragma unroll
            for (int v = 0; v < 4; v++) bv[v] = ws[c0 + v][k];
#pragma unroll
            for (int u = 0; u < 4; u++)
#pragma unroll
                for (int v = 0; v < 4; v++)
                    acc[u][v] = fmaf(a[u], bv[v], acc[u][v]);
        }
        __syncthreads();
    }
#pragma unroll
    for (int u = 0; u < 4; u++) {
        float s = 0.f;
#pragma unroll
        for (int v = 0; v < 4; v++) s = fmaf(acc[u][v], acc[u][v], s);
        rowsq[r0 + u][cg] = s;
    }
    __syncthreads();
    if (tid < 32) {
        float s = 0.f;
#pragma unroll
        for (int c = 0; c < 16; c++) s += rowsq[tid][c];
        float m = sqrtf(s);
        g_gn[rowBase + tid] = m;
        inv_s[tid] = 1.f / fmaxf(m, 1e-12f);
    }
    __syncthreads();
#pragma unroll
    for (int u = 0; u < 4; u++) {
        float iv = inv_s[r0 + u];
        float4 o;
        o.x = acc[u][0] * iv; o.y = acc[u][1] * iv;
        o.z = acc[u][2] * iv; o.w = acc[u][3] * iv;
        *reinterpret_cast<float4*>(&g_gu[(size_t)(rowBase + r0 + u) * GD + c0]) = o;
    }
}

// =====================================================================
// K2: sim = gu @ gu^T; 32x32 tiles, 64 threads, thread = 4x4.
// sim bitwise symmetric (same k-order both sides) — required.
// =====================================================================
__global__ void __launch_bounds__(64) k_sim() {
    __shared__ float A[32][65], Bm[32][65];
    const int b = blockIdx.z, i0 = blockIdx.y * 32, j0 = blockIdx.x * 32;
    const int tid = threadIdx.x;
#pragma unroll
    for (int it = 0; it < 8; it++) {
        int idx = tid + it * 64;
        int rr = idx >> 4, kk = (idx & 15) << 2;
        float4 v = *reinterpret_cast<const float4*>(
            &g_gu[((size_t)b * LL + i0 + rr) * GD + kk]);
        A[rr][kk] = v.x; A[rr][kk + 1] = v.y; A[rr][kk + 2] = v.z; A[rr][kk + 3] = v.w;
        float4 w = *reinterpret_cast<const float4*>(
            &g_gu[((size_t)b * LL + j0 + rr) * GD + kk]);
        Bm[rr][kk] = w.x; Bm[rr][kk + 1] = w.y; Bm[rr][kk + 2] = w.z; Bm[rr][kk + 3] = w.w;
    }
    __syncthreads();
    const int rg = tid & 7, cg = tid >> 3;
    const int r0 = rg * 4, c0 = cg * 4;
    float acc[4][4];
#pragma unroll
    for (int u = 0; u < 4; u++)
#pragma unroll
        for (int v = 0; v < 4; v++) acc[u][v] = 0.f;
#pragma unroll 8
    for (int k = 0; k < GD; k++) {
        float a[4], bv[4];
#pragma unroll
        for (int u = 0; u < 4; u++) a[u] = A[r0 + u][k];
#pragma unroll
        for (int v = 0; v < 4; v++) bv[v] = Bm[c0 + v][k];
#pragma unroll
        for (int u = 0; u < 4; u++)
#pragma unroll
            for (int v = 0; v < 4; v++)
                acc[u][v] = fmaf(a[u], bv[v], acc[u][v]);
    }
#pragma unroll
    for (int u = 0; u < 4; u++) {
        float4 o;
        o.x = acc[u][0]; o.y = acc[u][1]; o.z = acc[u][2]; o.w = acc[u][3];
        *reinterpret_cast<float4*>(
            &g_sim[((size_t)b * LL + i0 + r0 + u) * LL + j0 + c0]) = o;
    }
}

// =====================================================================
// K3: per-row top-16 candidate keys via REDUX-based selection.
// Within a row, full-key order == (simkey asc, then column asc) —
// resolved with two u32 __reduce_min_sync ops. Bitwise-identical lists.
// =====================================================================
__global__ void __launch_bounds__(256) k_lists() {
    const int warp = threadIdx.x >> 5, lane = threadIdx.x & 31;
    const int rr = blockIdx.x * 8 + warp;      // 0..4095 flattened
    const int r = rr & (LL - 1);
    const float4* row4 = reinterpret_cast<const float4*>(&g_sim[(size_t)rr * LL]);
    unsigned sk[16];
#pragma unroll
    for (int q = 0; q < 4; q++) {
        float4 v = row4[lane + q * 32];
        float f[4] = {v.x, v.y, v.z, v.w};
        int cbase = (lane + q * 32) * 4;
#pragma unroll
        for (int e = 0; e < 4; e++) {
            int cc = cbase + e;
            sk[q * 4 + e] = (cc == r) ? 0xFFFFFFFFu : ~ordf(f[e]);
        }
    }
    unsigned long long* out = &g_lists[(size_t)rr * TL];
    for (int t = 0; t < TL; t++) {
        unsigned lm = 0xFFFFFFFFu; int le = 0;
#pragma unroll
        for (int s = 0; s < 16; s++) if (sk[s] < lm) { lm = sk[s]; le = s; }
        unsigned m = __reduce_min_sync(0xffffffffu, lm);
        int lcc = (lane + (le >> 2) * 32) * 4 + (le & 3);
        unsigned cprop = (lm == m) ? (unsigned)lcc : 0xFFFFu;
        unsigned cmin = __reduce_min_sync(0xffffffffu, cprop);
        if (lm == m && (unsigned)lcc == cmin) sk[le] = 0xFFFFFFFFu;
        if (lane == 0) out[t] = keyfrom(m, r, (int)cmin);
    }
}

// =====================================================================
// K4: greedy matching via iterated mutual-best rounds with smem top-16
// lists; phase-C = single best-available pick via REDUX (R3-proven
// configuration, cheaper reduction). Selected set identical to
// sequential greedy.
// =====================================================================
__global__ void __launch_bounds__(512) k_greedy() {
    extern __shared__ unsigned long long sl[];   // LL*TLP keys (69.6 KB)
    __shared__ unsigned long long best[LL];
    __shared__ unsigned char hd[LL];
    __shared__ unsigned used[16];
    __shared__ short qrows[LL];
    __shared__ int qn, nsel;
    __shared__ short sel_i[KK], sel_j[KK];
    __shared__ unsigned ibits[16];

    const int b = blockIdx.x, tid = threadIdx.x;
    const int warp = tid >> 5, lane = tid & 31;
    const float* simb = &g_sim[(size_t)b * LL * LL];

    // copy lists (stride-16 global -> stride-17 smem)
#pragma unroll
    for (int q = 0; q < TL; q++) {
        int idx = tid + q * 512;                 // 0..8191
        sl[(size_t)(idx >> 4) * TLP + (idx & 15)] = g_lists[(size_t)b * LL * TL + idx];
    }
    if (tid < 16) { used[tid] = 0u; ibits[tid] = 0u; }
    if (tid == 0) { nsel = 0; qn = 0; }
    __syncthreads();
    best[tid] = sl[(size_t)tid * TLP];
    hd[tid] = 1;
    __syncthreads();

    while (true) {
        // --- phase A: mutual-best selection (thread per row) ---
        {
            const int r = tid;
            if (!((used[r >> 5] >> (r & 31)) & 1u)) {
                unsigned long long k = best[r];
                int a = (int)((k >> 9) & 511), d = (int)(k & 511);
                if (r == a && best[d] == k) {    // mutual; select once at min endpoint
                    int s = atomicAdd(&nsel, 1);
                    sel_i[s] = (short)a; sel_j[s] = (short)d;
                    atomicOr(&used[a >> 5], 1u << (a & 31));
                    atomicOr(&used[d >> 5], 1u << (d & 31));
                }
            }
            if (tid == 0) qn = 0;
        }
        __syncthreads();
        if (nsel >= KK) break;

        // --- phase B: advance dead rows via smem list; queue exhausted ---
        {
            const int r = tid;
            if (!((used[r >> 5] >> (r & 31)) & 1u)) {
                unsigned long long k = best[r];
                int a = (int)((k >> 9) & 511), d = (int)(k & 511);
                int p = a ^ d ^ r;
                if ((used[p >> 5] >> (p & 31)) & 1u) {   // cached best died
                    int h = hd[r];
                    unsigned long long nb = ~0ULL;
                    while (h < TL) {
                        unsigned long long e = sl[(size_t)r * TLP + h]; h++;
                        int p2 = ((int)((e >> 9) & 511)) ^ ((int)(e & 511)) ^ r;
                        if (!((used[p2 >> 5] >> (p2 & 31)) & 1u)) { nb = e; break; }
                    }
                    hd[r] = (unsigned char)h;
                    if (nb != ~0ULL) best[r] = nb;
                    else qrows[atomicAdd(&qn, 1)] = (short)r;
                }
            }
        }
        __syncthreads();

        // --- phase C: warp-parallel full rescans, top-1 via REDUX ---
        for (int qi = warp; qi < qn; qi += 16) {
            const int r = qrows[qi];
            const float4* row4 = reinterpret_cast<const float4*>(&simb[(size_t)r * LL]);
            float4 v[4];
#pragma unroll
            for (int q = 0; q < 4; q++) v[q] = row4[lane + q * 32];
            unsigned lm = 0xFFFFFFFFu; int lcc = 0;
#pragma unroll
            for (int q = 0; q < 4; q++) {
                float f[4] = {v[q].x, v[q].y, v[q].z, v[q].w};
                int cbase = (lane + q * 32) * 4;
#pragma unroll
                for (int e = 0; e < 4; e++) {
                    int cc = cbase + e;
                    if (cc == r) continue;
                    if ((used[cc >> 5] >> (cc & 31)) & 1u) continue;
                    unsigned kk = ~ordf(f[e]);
                    if (kk < lm) { lm = kk; lcc = cc; }
                }
            }
            unsigned m = __reduce_min_sync(0xffffffffu, lm);
            unsigned cprop = (lm == m) ? (unsigned)lcc : 0xFFFFu;
            unsigned cmin = __reduce_min_sync(0xffffffffu, cprop);
            if (lane == 0) best[r] = keyfrom(m, r, (int)cmin);
        }
        __syncthreads();
    }

    // --- emit kept-slot pair records (rank = position of i among sorted i's) ---
    if (tid < KK) atomicOr(&ibits[sel_i[tid] >> 5], 1u << (sel_i[tid] & 31));
    __syncthreads();
    if (tid < KK) {
        int i = sel_i[tid], j = sel_j[tid];
        int rank = 0;
        for (int w2 = 0; w2 < (i >> 5); w2++) rank += __popc(ibits[w2]);
        rank += __popc(ibits[i >> 5] & ((1u << (i & 31)) - 1u));
        float wi = g_gn[b * LL + i], wj = g_gn[b * LL + j];
        g_pairs[b * KK + rank] = make_int4(i, j, __float_as_int(wi), __float_as_int(wj));
    }
}

// =====================================================================
// K5: merge outputs — streaming loads/stores (data touched exactly once)
// =====================================================================
__global__ void __launch_bounds__(256) k_merge(const float* __restrict__ x,
                                               const float* __restrict__ src,
                                               float* __restrict__ out) {
    const int blk = blockIdx.x;
    const int b = blk >> 8, slot = blk & 255;
    int4 p = g_pairs[blk];
    const int i = p.x, j = p.y;
    const float wi = __int_as_float(p.z), wj = __int_as_float(p.w);
    const float tot = wi + wj + 1e-8f;
    const float ai = wi / tot, aj = wj / tot;
    const int t = threadIdx.x;

    const float4* xi = reinterpret_cast<const float4*>(&x[((size_t)b * LL + i) * DD]);
    const float4* xj = reinterpret_cast<const float4*>(&x[((size_t)b * LL + j) * DD]);
    float4* xo = reinterpret_cast<float4*>(&out[((size_t)b * KK + slot) * DD]);
    {
        float4 a = __ldcs(&xi[t]), c = __ldcs(&xj[t]), o;
        o.x = fmaf(ai, a.x, aj * c.x);
        o.y = fmaf(ai, a.y, aj * c.y);
        o.z = fmaf(ai, a.z, aj * c.z);
        o.w = fmaf(ai, a.w, aj * c.w);
        __stcs(&xo[t], o);
    }
    const float4* si = reinterpret_cast<const float4*>(&src[((size_t)b * LL + i) * NN]);
    const float4* sj = reinterpret_cast<const float4*>(&src[((size_t)b * LL + j) * NN]);
    float4* so = reinterpret_cast<float4*>(
        &out[(size_t)BB * KK * DD + ((size_t)b * KK + slot) * NN]);
#pragma unroll
    for (int q = 0; q < 8; q++) {
        int idx = t + q * 256;
        float4 a = __ldcs(&si[idx]), c = __ldcs(&sj[idx]), o;
        o.x = a.x + c.x; o.y = a.y + c.y; o.z = a.z + c.z; o.w = a.w + c.w;
        __stcs(&so[idx], o);
    }
}

// =====================================================================
extern "C" void kernel_launch(void* const* d_in, const int* in_sizes, int n_in,
                              void* d_out, int out_size) {
    const float* x = nullptr;
    const float* src = nullptr;
    const float* W = nullptr;
    for (int k = 0; k < n_in; k++) {
        if (in_sizes[k] == BB * LL * DD) x = (const float*)d_in[k];
        else if (in_sizes[k] == BB * LL * NN) src = (const float*)d_in[k];
        else if (in_sizes[k] == GD * DD) W = (const float*)d_in[k];
    }
    float* out = (float*)d_out;

    cudaFuncSetAttribute(k_greedy, cudaFuncAttributeMaxDynamicSharedMemorySize,
                         LL * TLP * (int)sizeof(unsigned long long));

    k_proj<<<(BB * LL) / 32, 128>>>(x, W);
    dim3 gsim(16, 16, BB);
    k_sim<<<gsim, 64>>>();
    k_lists<<<(BB * LL) / 8, 256>>>();
    k_greedy<<<BB, 512, LL * TLP * sizeof(unsigned long long)>>>();
    k_merge<<<BB * KK, 256>>>(x, src, out);
}